// round 2
// baseline (speedup 1.0000x reference)
#include <cuda_runtime.h>

#define N_TOK 4096
#define DM    512
#define NH    8
#define DKH   64
#define DFF   2048

// ---------------- scratch (device globals; no runtime allocation) ----------
__device__ float g_Q[N_TOK * DM];
__device__ float g_K[N_TOK * DM];
__device__ float g_V[N_TOK * DM];
__device__ float g_ctx[N_TOK * DM];
__device__ float g_tmp[N_TOK * DM];
__device__ float g_h1[N_TOK * DM];
__device__ float g_ff[(size_t)N_TOK * DFF];

// ---------------------------------------------------------------------------
// C[m,n] = sum_k A[m,k] * B[n,k] + bias[n]   (optionally ReLU)
// A: [M,K] row-major, B: [Nn,K] row-major. M,Nn multiples of 64, K mult of 16.
// 64x64 tile, 256 threads, 4x4 per-thread microtile, double-buffered smem.
// ---------------------------------------------------------------------------
template <bool RELU>
__device__ __forceinline__ void gemm_bt_body(const float* __restrict__ A,
                                             const float* __restrict__ B,
                                             const float* __restrict__ bias,
                                             float* __restrict__ C,
                                             int M, int Nn, int K)
{
    __shared__ float AsT[2][16][64];   // [buf][k][m]
    __shared__ float BsT[2][16][64];   // [buf][k][n]

    const int tid = threadIdx.x;
    const int tx  = tid & 15;       // 0..15 -> n group
    const int ty  = tid >> 4;       // 0..15 -> m group
    const int m0  = blockIdx.y * 64;
    const int n0  = blockIdx.x * 64;

    const int lr = tid >> 2;        // 0..63 row within tile
    const int lk = (tid & 3) * 4;   // 0,4,8,12 k offset

    float acc[4][4] = {};

    // preload first k-tile
    {
        float4 av = *reinterpret_cast<const float4*>(&A[(size_t)(m0 + lr) * K + lk]);
        float4 bv = *reinterpret_cast<const float4*>(&B[(size_t)(n0 + lr) * K + lk]);
        AsT[0][lk + 0][lr] = av.x; AsT[0][lk + 1][lr] = av.y;
        AsT[0][lk + 2][lr] = av.z; AsT[0][lk + 3][lr] = av.w;
        BsT[0][lk + 0][lr] = bv.x; BsT[0][lk + 1][lr] = bv.y;
        BsT[0][lk + 2][lr] = bv.z; BsT[0][lk + 3][lr] = bv.w;
    }
    __syncthreads();

    int buf = 0;
    for (int k0 = 0; k0 < K; k0 += 16) {
        const bool has_next = (k0 + 16) < K;
        float4 av2, bv2;
        if (has_next) {
            av2 = *reinterpret_cast<const float4*>(&A[(size_t)(m0 + lr) * K + k0 + 16 + lk]);
            bv2 = *reinterpret_cast<const float4*>(&B[(size_t)(n0 + lr) * K + k0 + 16 + lk]);
        }

        #pragma unroll
        for (int kk = 0; kk < 16; kk++) {
            float4 a = *reinterpret_cast<const float4*>(&AsT[buf][kk][ty * 4]);
            float4 b = *reinterpret_cast<const float4*>(&BsT[buf][kk][tx * 4]);
            float ar[4] = {a.x, a.y, a.z, a.w};
            float br[4] = {b.x, b.y, b.z, b.w};
            #pragma unroll
            for (int i = 0; i < 4; i++)
                #pragma unroll
                for (int j = 0; j < 4; j++)
                    acc[i][j] = fmaf(ar[i], br[j], acc[i][j]);
        }

        if (has_next) {
            const int nb = buf ^ 1;
            AsT[nb][lk + 0][lr] = av2.x; AsT[nb][lk + 1][lr] = av2.y;
            AsT[nb][lk + 2][lr] = av2.z; AsT[nb][lk + 3][lr] = av2.w;
            BsT[nb][lk + 0][lr] = bv2.x; BsT[nb][lk + 1][lr] = bv2.y;
            BsT[nb][lk + 2][lr] = bv2.z; BsT[nb][lk + 3][lr] = bv2.w;
            __syncthreads();
            buf = nb;
        }
    }

    #pragma unroll
    for (int i = 0; i < 4; i++) {
        const int m = m0 + ty * 4 + i;
        float4 out;
        float* o = &out.x;
        #pragma unroll
        for (int j = 0; j < 4; j++) {
            const int n = n0 + tx * 4 + j;
            float v = acc[i][j] + bias[n];
            if (RELU) v = fmaxf(v, 0.0f);
            o[j] = v;
        }
        *reinterpret_cast<float4*>(&C[(size_t)m * Nn + n0 + tx * 4]) = out;
    }
}

template <bool RELU>
__global__ __launch_bounds__(256) void gemm_bt(const float* __restrict__ A,
                                               const float* __restrict__ B,
                                               const float* __restrict__ bias,
                                               float* __restrict__ C,
                                               int M, int Nn, int K)
{
    gemm_bt_body<RELU>(A, B, bias, C, M, Nn, K);
}

// Fused QKV: gridDim.z = 3 selects (Wq,bq,Q) / (Wk,bk,K) / (Wv,bv,V)
__global__ __launch_bounds__(256) void gemm_qkv(const float* __restrict__ A,
                                                const float* __restrict__ Wq,
                                                const float* __restrict__ bq,
                                                const float* __restrict__ Wk,
                                                const float* __restrict__ bk,
                                                const float* __restrict__ Wv,
                                                const float* __restrict__ bv,
                                                float* __restrict__ Qo,
                                                float* __restrict__ Ko,
                                                float* __restrict__ Vo)
{
    const float* B;
    const float* bias;
    float* C;
    if (blockIdx.z == 0)      { B = Wq; bias = bq; C = Qo; }
    else if (blockIdx.z == 1) { B = Wk; bias = bk; C = Ko; }
    else                      { B = Wv; bias = bv; C = Vo; }
    gemm_bt_body<false>(A, B, bias, C, N_TOK, DM, DM);
}

// ---------------------------------------------------------------------------
// Flash attention: one block per (64-query tile, head). 256 threads.
// Online softmax, adj mask (adj==0 && q!=k -> -1e9) read from global (L2-hot).
// ---------------------------------------------------------------------------
__global__ __launch_bounds__(256) void attn_kernel(const float* __restrict__ Q,
                                                   const float* __restrict__ K,
                                                   const float* __restrict__ V,
                                                   const int* __restrict__ adj,
                                                   float* __restrict__ ctx)
{
    __shared__ float QsT[64][64];   // [k][qrow], prescaled by 1/8
    __shared__ float KVs[64][64];   // phase 1: K^T [k][kvcol]; phase 2: V [kv][d]
    __shared__ float Ss[64][64];    // P [qrow][kvcol]

    const int tid = threadIdx.x;
    const int tx  = tid & 15;
    const int ty  = tid >> 4;
    const int h   = blockIdx.y;
    const int q0  = blockIdx.x * 64;

    // load Q tile transposed, prescaled
    for (int t = tid; t < 1024; t += 256) {
        const int r  = t >> 4;
        const int kq = (t & 15) * 4;
        float4 v = *reinterpret_cast<const float4*>(&Q[(size_t)(q0 + r) * DM + h * DKH + kq]);
        QsT[kq + 0][r] = v.x * 0.125f;
        QsT[kq + 1][r] = v.y * 0.125f;
        QsT[kq + 2][r] = v.z * 0.125f;
        QsT[kq + 3][r] = v.w * 0.125f;
    }

    float m_i[4], l_i[4], o[4][4];
    #pragma unroll
    for (int i = 0; i < 4; i++) {
        m_i[i] = -INFINITY;
        l_i[i] = 0.0f;
        #pragma unroll
        for (int j = 0; j < 4; j++) o[i][j] = 0.0f;
    }

    for (int kb = 0; kb < N_TOK / 64; kb++) {
        const int k0 = kb * 64;

        // load K tile transposed into KVs
        __syncthreads();   // prior PV reads done
        for (int t = tid; t < 1024; t += 256) {
            const int r  = t >> 4;
            const int kq = (t & 15) * 4;
            float4 v = *reinterpret_cast<const float4*>(&K[(size_t)(k0 + r) * DM + h * DKH + kq]);
            KVs[kq + 0][r] = v.x; KVs[kq + 1][r] = v.y;
            KVs[kq + 2][r] = v.z; KVs[kq + 3][r] = v.w;
        }
        __syncthreads();

        // S = (Q/8) @ K^T   (64x64, each thread 4x4)
        float s[4][4] = {};
        #pragma unroll
        for (int kk = 0; kk < 64; kk++) {
            float4 qa = *reinterpret_cast<const float4*>(&QsT[kk][ty * 4]);
            float4 ka = *reinterpret_cast<const float4*>(&KVs[kk][tx * 4]);
            float qr[4] = {qa.x, qa.y, qa.z, qa.w};
            float kr[4] = {ka.x, ka.y, ka.z, ka.w};
            #pragma unroll
            for (int i = 0; i < 4; i++)
                #pragma unroll
                for (int j = 0; j < 4; j++)
                    s[i][j] = fmaf(qr[i], kr[j], s[i][j]);
        }

        // mask + online softmax, per owned query row
        #pragma unroll
        for (int i = 0; i < 4; i++) {
            const int gq = q0 + ty * 4 + i;
            int4 a4 = *reinterpret_cast<const int4*>(&adj[(size_t)gq * N_TOK + k0 + tx * 4]);
            const int av[4] = {a4.x, a4.y, a4.z, a4.w};
            #pragma unroll
            for (int j = 0; j < 4; j++) {
                const int gk = k0 + tx * 4 + j;
                if (av[j] == 0 && gq != gk) s[i][j] = -1e9f;
            }
            float rm = fmaxf(fmaxf(s[i][0], s[i][1]), fmaxf(s[i][2], s[i][3]));
            #pragma unroll
            for (int off = 8; off >= 1; off >>= 1)
                rm = fmaxf(rm, __shfl_xor_sync(0xffffffffu, rm, off, 16));
            const float mn    = fmaxf(m_i[i], rm);
            const float scale = __expf(m_i[i] - mn);
            float p[4], ps = 0.0f;
            #pragma unroll
            for (int j = 0; j < 4; j++) { p[j] = __expf(s[i][j] - mn); ps += p[j]; }
            #pragma unroll
            for (int off = 8; off >= 1; off >>= 1)
                ps += __shfl_xor_sync(0xffffffffu, ps, off, 16);
            l_i[i] = l_i[i] * scale + ps;
            m_i[i] = mn;
            #pragma unroll
            for (int j = 0; j < 4; j++) o[i][j] *= scale;
            float4 pv = make_float4(p[0], p[1], p[2], p[3]);
            *reinterpret_cast<float4*>(&Ss[ty * 4 + i][tx * 4]) = pv;
        }
        __syncthreads();   // Ss complete, KVs(K) reads done

        // load V tile (natural layout) into KVs
        for (int t = tid; t < 1024; t += 256) {
            const int r  = t >> 4;
            const int dq = (t & 15) * 4;
            *reinterpret_cast<float4*>(&KVs[r][dq]) =
                *reinterpret_cast<const float4*>(&V[(size_t)(k0 + r) * DM + h * DKH + dq]);
        }
        __syncthreads();

        // O += P @ V
        #pragma unroll
        for (int kk = 0; kk < 64; kk++) {
            float4 va = *reinterpret_cast<const float4*>(&KVs[kk][tx * 4]);
            float vr[4] = {va.x, va.y, va.z, va.w};
            float pr[4];
            #pragma unroll
            for (int i = 0; i < 4; i++) pr[i] = Ss[ty * 4 + i][kk];
            #pragma unroll
            for (int i = 0; i < 4; i++)
                #pragma unroll
                for (int j = 0; j < 4; j++)
                    o[i][j] = fmaf(pr[i], vr[j], o[i][j]);
        }
    }

    // epilogue: normalize and write ctx slice for this head
    #pragma unroll
    for (int i = 0; i < 4; i++) {
        const float inv = 1.0f / l_i[i];
        float4 out = make_float4(o[i][0] * inv, o[i][1] * inv, o[i][2] * inv, o[i][3] * inv);
        *reinterpret_cast<float4*>(&ctx[(size_t)(q0 + ty * 4 + i) * DM + h * DKH + tx * 4]) = out;
    }
}

// ---------------------------------------------------------------------------
// out = LayerNorm(x + r) * g + b, one block (128 threads) per row of 512
// ---------------------------------------------------------------------------
__global__ __launch_bounds__(128) void ln_kernel(const float* __restrict__ x,
                                                 const float* __restrict__ r,
                                                 const float* __restrict__ g,
                                                 const float* __restrict__ b,
                                                 float* __restrict__ out)
{
    __shared__ float ws[4], ws2[4];
    const int row = blockIdx.x;
    const int tid = threadIdx.x;
    const int col = tid * 4;

    float4 xv = *reinterpret_cast<const float4*>(&x[(size_t)row * DM + col]);
    float4 rv = *reinterpret_cast<const float4*>(&r[(size_t)row * DM + col]);
    float v[4] = {xv.x + rv.x, xv.y + rv.y, xv.z + rv.z, xv.w + rv.w};

    float s = 0.0f, s2 = 0.0f;
    #pragma unroll
    for (int c = 0; c < 4; c++) { s += v[c]; s2 = fmaf(v[c], v[c], s2); }

    #pragma unroll
    for (int off = 16; off >= 1; off >>= 1) {
        s  += __shfl_xor_sync(0xffffffffu, s,  off);
        s2 += __shfl_xor_sync(0xffffffffu, s2, off);
    }
    const int wid = tid >> 5;
    if ((tid & 31) == 0) { ws[wid] = s; ws2[wid] = s2; }
    __syncthreads();
    const float S  = ws[0] + ws[1] + ws[2] + ws[3];
    const float S2 = ws2[0] + ws2[1] + ws2[2] + ws2[3];
    const float mean = S * (1.0f / DM);
    const float var  = S2 * (1.0f / DM) - mean * mean;
    const float rstd = rsqrtf(var + 1e-5f);

    float4 gv = *reinterpret_cast<const float4*>(&g[col]);
    float4 bv = *reinterpret_cast<const float4*>(&b[col]);
    float gr[4] = {gv.x, gv.y, gv.z, gv.w};
    float br[4] = {bv.x, bv.y, bv.z, bv.w};
    float4 ov;
    float* op = &ov.x;
    #pragma unroll
    for (int c = 0; c < 4; c++)
        op[c] = (v[c] - mean) * rstd * gr[c] + br[c];
    *reinterpret_cast<float4*>(&out[(size_t)row * DM + col]) = ov;
}

// ---------------------------------------------------------------------------
extern "C" void kernel_launch(void* const* d_in, const int* in_sizes, int n_in,
                              void* d_out, int out_size)
{
    const float* h    = (const float*)d_in[0];
    const int*   adj  = (const int*)d_in[1];
    const float* Wq   = (const float*)d_in[2];
    const float* bq   = (const float*)d_in[3];
    const float* Wk   = (const float*)d_in[4];
    const float* bk   = (const float*)d_in[5];
    const float* Wv   = (const float*)d_in[6];
    const float* bv   = (const float*)d_in[7];
    const float* Wo   = (const float*)d_in[8];
    const float* bo   = (const float*)d_in[9];
    const float* W1   = (const float*)d_in[10];
    const float* b1   = (const float*)d_in[11];
    const float* W2   = (const float*)d_in[12];
    const float* b2   = (const float*)d_in[13];
    const float* ln1g = (const float*)d_in[14];
    const float* ln1b = (const float*)d_in[15];
    const float* ln2g = (const float*)d_in[16];
    const float* ln2b = (const float*)d_in[17];
    float* out = (float*)d_out;

    float *Qd, *Kd, *Vd, *ctx, *tmp, *h1, *ff;
    cudaGetSymbolAddress((void**)&Qd,  g_Q);
    cudaGetSymbolAddress((void**)&Kd,  g_K);
    cudaGetSymbolAddress((void**)&Vd,  g_V);
    cudaGetSymbolAddress((void**)&ctx, g_ctx);
    cudaGetSymbolAddress((void**)&tmp, g_tmp);
    cudaGetSymbolAddress((void**)&h1,  g_h1);
    cudaGetSymbolAddress((void**)&ff,  g_ff);

    const dim3 blk(256);
    const dim3 gQKV(DM / 64, N_TOK / 64, 3); // fused Q/K/V projections
    const dim3 gP(DM / 64, N_TOK / 64);      // 512-wide GEMMs
    const dim3 gF1(DFF / 64, N_TOK / 64);    // FF1: N=2048
    const dim3 gA(N_TOK / 64, NH);           // attention

    gemm_qkv<<<gQKV, blk>>>(h, Wq, bq, Wk, bk, Wv, bv, Qd, Kd, Vd);

    attn_kernel<<<gA, blk>>>(Qd, Kd, Vd, adj, ctx);

    gemm_bt<false><<<gP, blk>>>(ctx, Wo, bo, tmp, N_TOK, DM, DM);
    ln_kernel<<<N_TOK, 128>>>(h, tmp, ln1g, ln1b, h1);

    gemm_bt<true ><<<gF1, blk>>>(h1, W1, b1, ff, N_TOK, DFF, DM);
    gemm_bt<false><<<gP,  blk>>>(ff, W2, b2, tmp, N_TOK, DM, DFF);
    ln_kernel<<<N_TOK, 128>>>(h1, tmp, ln2g, ln2b, out);
}

// round 6
// speedup vs baseline: 1.3338x; 1.3338x over previous
#include <cuda_runtime.h>
#include <cuda_bf16.h>
#include <cstdint>

#define N_TOK 4096
#define DM    512
#define NH    8
#define DKH   64
#define DFF   2048

// ---------------- scratch (device globals; no runtime allocation) ----------
__device__ float g_Q[N_TOK * DM];
__device__ float g_K[N_TOK * DM];
__device__ float g_V[N_TOK * DM];
__device__ float g_ctx[N_TOK * DM];
__device__ float g_tmp[N_TOK * DM];
__device__ float g_h1[N_TOK * DM];
__device__ float g_ff[(size_t)N_TOK * DFF];

// bf16 hi/lo planes
__device__ __nv_bfloat16 g_hb_hi[N_TOK * DM],  g_hb_lo[N_TOK * DM];
__device__ __nv_bfloat16 g_cx_hi[N_TOK * DM],  g_cx_lo[N_TOK * DM];
__device__ __nv_bfloat16 g_h1_hi[N_TOK * DM],  g_h1_lo[N_TOK * DM];
__device__ __nv_bfloat16 g_ff_hi[(size_t)N_TOK * DFF], g_ff_lo[(size_t)N_TOK * DFF];
// weights concatenated: Wq,Wk,Wv,Wo (512x512 each), W1 (2048x512), W2 (512x2048)
#define WOFF_Q  0
#define WOFF_K  (512 * 512)
#define WOFF_V  (2 * 512 * 512)
#define WOFF_O  (3 * 512 * 512)
#define WOFF_1  (4 * 512 * 512)
#define WOFF_2  (4 * 512 * 512 + 2048 * 512)
#define WTOT    (4 * 512 * 512 + 2 * 2048 * 512)
__device__ __nv_bfloat16 g_w_hi[WTOT], g_w_lo[WTOT];

// ===================== low-level helpers ==================================
__device__ __forceinline__ uint32_t smem_u32(const void* p) {
    uint32_t a;
    asm("{ .reg .u64 t; cvta.to.shared.u64 t, %1; cvt.u32.u64 %0, t; }"
        : "=r"(a) : "l"(p));
    return a;
}
__device__ __forceinline__ void cp16(uint32_t dst, const void* src) {
    asm volatile("cp.async.cg.shared.global [%0], [%1], 16;" :: "r"(dst), "l"(src));
}
__device__ __forceinline__ void cp_commit_wait() {
    asm volatile("cp.async.commit_group;");
    asm volatile("cp.async.wait_group 0;" ::: "memory");
}
__device__ __forceinline__ void ldm_x4(uint32_t* r, uint32_t addr) {
    asm volatile("ldmatrix.sync.aligned.m8n8.x4.shared.b16 {%0,%1,%2,%3}, [%4];"
                 : "=r"(r[0]), "=r"(r[1]), "=r"(r[2]), "=r"(r[3]) : "r"(addr));
}
__device__ __forceinline__ void mma_bf16(float* d, const uint32_t* a, const uint32_t* b) {
    asm volatile("mma.sync.aligned.m16n8k16.row.col.f32.bf16.bf16.f32 "
                 "{%0,%1,%2,%3},{%4,%5,%6,%7},{%8,%9},{%0,%1,%2,%3};"
                 : "+f"(d[0]), "+f"(d[1]), "+f"(d[2]), "+f"(d[3])
                 : "r"(a[0]), "r"(a[1]), "r"(a[2]), "r"(a[3]),
                   "r"(b[0]), "r"(b[1]));
}

// ===================== fp32 -> bf16 hi/lo conversion ======================
__global__ __launch_bounds__(256) void convert_split(const float* __restrict__ in,
                                                     __nv_bfloat16* __restrict__ hi,
                                                     __nv_bfloat16* __restrict__ lo,
                                                     int n)
{
    int i = (blockIdx.x * 256 + threadIdx.x) * 4;
    if (i >= n) return;
    float4 v = *reinterpret_cast<const float4*>(in + i);
    __nv_bfloat16 hx = __float2bfloat16(v.x), hy = __float2bfloat16(v.y);
    __nv_bfloat16 hz = __float2bfloat16(v.z), hw = __float2bfloat16(v.w);
    __nv_bfloat162 h0; h0.x = hx; h0.y = hy;
    __nv_bfloat162 h1; h1.x = hz; h1.y = hw;
    __nv_bfloat162 l0, l1;
    l0.x = __float2bfloat16(v.x - __bfloat162float(hx));
    l0.y = __float2bfloat16(v.y - __bfloat162float(hy));
    l1.x = __float2bfloat16(v.z - __bfloat162float(hz));
    l1.y = __float2bfloat16(v.w - __bfloat162float(hw));
    *reinterpret_cast<__nv_bfloat162*>(hi + i)     = h0;
    *reinterpret_cast<__nv_bfloat162*>(hi + i + 2) = h1;
    *reinterpret_cast<__nv_bfloat162*>(lo + i)     = l0;
    *reinterpret_cast<__nv_bfloat162*>(lo + i + 2) = l1;
}

// ===================== tensor-core split-bf16 GEMM ========================
// C[m,n] = sum_k A[m,k]*B[n,k] + bias[n]  (A,B given as bf16 hi/lo planes)
// block: 64x64 tile, 128 threads (4 warps, 2x2 warp grid, 32x32 warp tile)
// smem rows: 32 bf16 (64B data), stride 80B -> conflict-free ldmatrix.

#define SROW 80

template <bool RELU>
__device__ __forceinline__ void gemm_mma_body(const __nv_bfloat16* __restrict__ Ahi,
                                              const __nv_bfloat16* __restrict__ Alo,
                                              const __nv_bfloat16* __restrict__ Bhi,
                                              const __nv_bfloat16* __restrict__ Blo,
                                              const float* __restrict__ bias,
                                              float* __restrict__ C,
                                              int Nn, int K)
{
    __shared__ __align__(128) uint8_t s_ahi[64 * SROW];
    __shared__ __align__(128) uint8_t s_alo[64 * SROW];
    __shared__ __align__(128) uint8_t s_bhi[64 * SROW];
    __shared__ __align__(128) uint8_t s_blo[64 * SROW];

    const int tid = threadIdx.x;
    const int lid = tid & 31;
    const int wid = tid >> 5;
    const int wm  = (wid >> 1) * 32;   // warp m offset in tile
    const int wn  = (wid & 1) * 32;    // warp n offset in tile
    const int m0  = blockIdx.y * 64;
    const int n0  = blockIdx.x * 64;

    const uint32_t sa_hi = smem_u32(s_ahi), sa_lo = smem_u32(s_alo);
    const uint32_t sb_hi = smem_u32(s_bhi), sb_lo = smem_u32(s_blo);

    // per-thread cp.async coordinates: 2 rows per plane
    const int r0 = tid >> 2, u0 = tid & 3;
    const int r1 = (tid + 128) >> 2;            // u1 == u0
    const int dst_off0 = r0 * SROW + u0 * 16;
    const int dst_off1 = r1 * SROW + u0 * 16;

    const __nv_bfloat16* gA_hi = Ahi + (size_t)m0 * K;
    const __nv_bfloat16* gA_lo = Alo + (size_t)m0 * K;
    const __nv_bfloat16* gB_hi = Bhi + (size_t)n0 * K;
    const __nv_bfloat16* gB_lo = Blo + (size_t)n0 * K;

    float acc[2][4][4] = {};

    // ldmatrix per-lane address offsets (byte offsets within planes)
    const int a_row = (lid & 15);
    const int a_sel = (lid >> 4);          // 0/1 -> k-half unit
    const int b_row = ((lid >> 4) & 1) * 8 + (lid & 7);
    const int b_sel = ((lid >> 3) & 1);

    const int nch = K >> 5;
    for (int c = 0; c < nch; c++) {
        const int k0 = c * 32;
        const int go0 = r0 * K + k0 + u0 * 8;
        const int go1 = r1 * K + k0 + u0 * 8;
        cp16(sa_hi + dst_off0, gA_hi + go0); cp16(sa_hi + dst_off1, gA_hi + go1);
        cp16(sa_lo + dst_off0, gA_lo + go0); cp16(sa_lo + dst_off1, gA_lo + go1);
        cp16(sb_hi + dst_off0, gB_hi + go0); cp16(sb_hi + dst_off1, gB_hi + go1);
        cp16(sb_lo + dst_off0, gB_lo + go0); cp16(sb_lo + dst_off1, gB_lo + go1);
        cp_commit_wait();
        __syncthreads();

        #pragma unroll
        for (int s = 0; s < 2; s++) {
            uint32_t afh[2][4], afl[2][4], bfh[2][4], bfl[2][4];
            #pragma unroll
            for (int mt = 0; mt < 2; mt++) {
                const uint32_t aoff = (uint32_t)((wm + mt * 16 + a_row) * SROW
                                                 + (s * 2 + a_sel) * 16);
                ldm_x4(afh[mt], sa_hi + aoff);
                ldm_x4(afl[mt], sa_lo + aoff);
            }
            #pragma unroll
            for (int q = 0; q < 2; q++) {
                const uint32_t boff = (uint32_t)((wn + q * 16 + b_row) * SROW
                                                 + (s * 2 + b_sel) * 16);
                ldm_x4(bfh[q], sb_hi + boff);
                ldm_x4(bfl[q], sb_lo + boff);
            }
            #pragma unroll
            for (int mt = 0; mt < 2; mt++)
                #pragma unroll
                for (int q = 0; q < 2; q++)
                    #pragma unroll
                    for (int t2 = 0; t2 < 2; t2++) {
                        float* d = acc[mt][q * 2 + t2];
                        mma_bf16(d, afh[mt], &bfh[q][t2 * 2]);
                        mma_bf16(d, afh[mt], &bfl[q][t2 * 2]);
                        mma_bf16(d, afl[mt], &bfh[q][t2 * 2]);
                    }
        }
        __syncthreads();
    }

    // epilogue
    #pragma unroll
    for (int mt = 0; mt < 2; mt++) {
        const int row = m0 + wm + mt * 16 + (lid >> 2);
        #pragma unroll
        for (int nt = 0; nt < 4; nt++) {
            const int col = n0 + wn + nt * 8 + (lid & 3) * 2;
            const float bx = bias[col], by = bias[col + 1];
            float2 v0, v1;
            v0.x = acc[mt][nt][0] + bx; v0.y = acc[mt][nt][1] + by;
            v1.x = acc[mt][nt][2] + bx; v1.y = acc[mt][nt][3] + by;
            if (RELU) {
                v0.x = fmaxf(v0.x, 0.0f); v0.y = fmaxf(v0.y, 0.0f);
                v1.x = fmaxf(v1.x, 0.0f); v1.y = fmaxf(v1.y, 0.0f);
            }
            *reinterpret_cast<float2*>(C + (size_t)row * Nn + col)       = v0;
            *reinterpret_cast<float2*>(C + (size_t)(row + 8) * Nn + col) = v1;
        }
    }
}

template <bool RELU>
__global__ __launch_bounds__(128) void gemm_mma(const __nv_bfloat16* __restrict__ Ahi,
                                                const __nv_bfloat16* __restrict__ Alo,
                                                const __nv_bfloat16* __restrict__ Bhi,
                                                const __nv_bfloat16* __restrict__ Blo,
                                                const float* __restrict__ bias,
                                                float* __restrict__ C,
                                                int Nn, int K)
{
    gemm_mma_body<RELU>(Ahi, Alo, Bhi, Blo, bias, C, Nn, K);
}

// fused QKV: z selects weight plane offset / bias / output
__global__ __launch_bounds__(128) void gemm_mma_qkv(const __nv_bfloat16* __restrict__ Ahi,
                                                    const __nv_bfloat16* __restrict__ Alo,
                                                    const float* __restrict__ bq,
                                                    const float* __restrict__ bk,
                                                    const float* __restrict__ bv,
                                                    float* __restrict__ Qo,
                                                    float* __restrict__ Ko,
                                                    float* __restrict__ Vo)
{
    const __nv_bfloat16* whi; const __nv_bfloat16* wlo;
    const float* bias; float* C;
    if (blockIdx.z == 0)      { whi = g_w_hi + WOFF_Q; wlo = g_w_lo + WOFF_Q; bias = bq; C = Qo; }
    else if (blockIdx.z == 1) { whi = g_w_hi + WOFF_K; wlo = g_w_lo + WOFF_K; bias = bk; C = Ko; }
    else                      { whi = g_w_hi + WOFF_V; wlo = g_w_lo + WOFF_V; bias = bv; C = Vo; }
    gemm_mma_body<false>(Ahi, Alo, whi, wlo, bias, C, DM, DM);
}

// ---------------------------------------------------------------------------
// Flash attention (known-good fp32): one block per (64-query tile, head).
// ---------------------------------------------------------------------------
__global__ __launch_bounds__(256) void attn_kernel(const float* __restrict__ Q,
                                                   const float* __restrict__ K,
                                                   const float* __restrict__ V,
                                                   const int* __restrict__ adj,
                                                   float* __restrict__ ctx)
{
    __shared__ float QsT[64][64];
    __shared__ float KVs[64][64];
    __shared__ float Ss[64][64];

    const int tid = threadIdx.x;
    const int tx  = tid & 15;
    const int ty  = tid >> 4;
    const int h   = blockIdx.y;
    const int q0  = blockIdx.x * 64;

    for (int t = tid; t < 1024; t += 256) {
        const int r  = t >> 4;
        const int kq = (t & 15) * 4;
        float4 v = *reinterpret_cast<const float4*>(&Q[(size_t)(q0 + r) * DM + h * DKH + kq]);
        QsT[kq + 0][r] = v.x * 0.125f;
        QsT[kq + 1][r] = v.y * 0.125f;
        QsT[kq + 2][r] = v.z * 0.125f;
        QsT[kq + 3][r] = v.w * 0.125f;
    }

    float m_i[4], l_i[4], o[4][4];
    #pragma unroll
    for (int i = 0; i < 4; i++) {
        m_i[i] = -INFINITY; l_i[i] = 0.0f;
        #pragma unroll
        for (int j = 0; j < 4; j++) o[i][j] = 0.0f;
    }

    for (int kb = 0; kb < N_TOK / 64; kb++) {
        const int k0 = kb * 64;
        __syncthreads();
        for (int t = tid; t < 1024; t += 256) {
            const int r  = t >> 4;
            const int kq = (t & 15) * 4;
            float4 v = *reinterpret_cast<const float4*>(&K[(size_t)(k0 + r) * DM + h * DKH + kq]);
            KVs[kq + 0][r] = v.x; KVs[kq + 1][r] = v.y;
            KVs[kq + 2][r] = v.z; KVs[kq + 3][r] = v.w;
        }
        __syncthreads();

        float s[4][4] = {};
        #pragma unroll
        for (int kk = 0; kk < 64; kk++) {
            float4 qa = *reinterpret_cast<const float4*>(&QsT[kk][ty * 4]);
            float4 ka = *reinterpret_cast<const float4*>(&KVs[kk][tx * 4]);
            float qr[4] = {qa.x, qa.y, qa.z, qa.w};
            float kr[4] = {ka.x, ka.y, ka.z, ka.w};
            #pragma unroll
            for (int i = 0; i < 4; i++)
                #pragma unroll
                for (int j = 0; j < 4; j++)
                    s[i][j] = fmaf(qr[i], kr[j], s[i][j]);
        }

        #pragma unroll
        for (int i = 0; i < 4; i++) {
            const int gq = q0 + ty * 4 + i;
            int4 a4 = *reinterpret_cast<const int4*>(&adj[(size_t)gq * N_TOK + k0 + tx * 4]);
            const int av[4] = {a4.x, a4.y, a4.z, a4.w};
            #pragma unroll
            for (int j = 0; j < 4; j++) {
                const int gk = k0 + tx * 4 + j;
                if (av[j] == 0 && gq != gk) s[i][j] = -1e9f;
            }
            float rm = fmaxf(fmaxf(s[i][0], s[i][1]), fmaxf(s[i][2], s[i][3]));
            #pragma unroll
            for (int off = 8; off >= 1; off >>= 1)
                rm = fmaxf(rm, __shfl_xor_sync(0xffffffffu, rm, off, 16));
            const float mn    = fmaxf(m_i[i], rm);
            const float scale = __expf(m_i[i] - mn);
            float p[4], ps = 0.0f;
            #pragma unroll
            for (int j = 0; j < 4; j++) { p[j] = __expf(s[i][j] - mn); ps += p[j]; }
            #pragma unroll
            for (int off = 8; off >= 1; off >>= 1)
                ps += __shfl_xor_sync(0xffffffffu, ps, off, 16);
            l_i[i] = l_i[i] * scale + ps;
            m_i[i] = mn;
            #pragma unroll
            for (int j = 0; j < 4; j++) o[i][j] *= scale;
            *reinterpret_cast<float4*>(&Ss[ty * 4 + i][tx * 4]) =
                make_float4(p[0], p[1], p[2], p[3]);
        }
        __syncthreads();

        for (int t = tid; t < 1024; t += 256) {
            const int r  = t >> 4;
            const int dq = (t & 15) * 4;
            *reinterpret_cast<float4*>(&KVs[r][dq]) =
                *reinterpret_cast<const float4*>(&V[(size_t)(k0 + r) * DM + h * DKH + dq]);
        }
        __syncthreads();

        #pragma unroll
        for (int kk = 0; kk < 64; kk++) {
            float4 va = *reinterpret_cast<const float4*>(&KVs[kk][tx * 4]);
            float vr[4] = {va.x, va.y, va.z, va.w};
            float pr[4];
            #pragma unroll
            for (int i = 0; i < 4; i++) pr[i] = Ss[ty * 4 + i][kk];
            #pragma unroll
            for (int i = 0; i < 4; i++)
                #pragma unroll
                for (int j = 0; j < 4; j++)
                    o[i][j] = fmaf(pr[i], vr[j], o[i][j]);
        }
    }

    #pragma unroll
    for (int i = 0; i < 4; i++) {
        const float inv = 1.0f / l_i[i];
        *reinterpret_cast<float4*>(&ctx[(size_t)(q0 + ty * 4 + i) * DM + h * DKH + tx * 4]) =
            make_float4(o[i][0] * inv, o[i][1] * inv, o[i][2] * inv, o[i][3] * inv);
    }
}

// ---------------------------------------------------------------------------
// out = LayerNorm(x + r) * g + b
// ---------------------------------------------------------------------------
__global__ __launch_bounds__(128) void ln_kernel(const float* __restrict__ x,
                                                 const float* __restrict__ r,
                                                 const float* __restrict__ g,
                                                 const float* __restrict__ b,
                                                 float* __restrict__ out)
{
    __shared__ float ws[4], ws2[4];
    const int row = blockIdx.x;
    const int tid = threadIdx.x;
    const int col = tid * 4;

    float4 xv = *reinterpret_cast<const float4*>(&x[(size_t)row * DM + col]);
    float4 rv = *reinterpret_cast<const float4*>(&r[(size_t)row * DM + col]);
    float v[4] = {xv.x + rv.x, xv.y + rv.y, xv.z + rv.z, xv.w + rv.w};

    float s = 0.0f, s2 = 0.0f;
    #pragma unroll
    for (int c = 0; c < 4; c++) { s += v[c]; s2 = fmaf(v[c], v[c], s2); }
    #pragma unroll
    for (int off = 16; off >= 1; off >>= 1) {
        s  += __shfl_xor_sync(0xffffffffu, s,  off);
        s2 += __shfl_xor_sync(0xffffffffu, s2, off);
    }
    const int wid = tid >> 5;
    if ((tid & 31) == 0) { ws[wid] = s; ws2[wid] = s2; }
    __syncthreads();
    const float S  = ws[0] + ws[1] + ws[2] + ws[3];
    const float S2 = ws2[0] + ws2[1] + ws2[2] + ws2[3];
    const float mean = S * (1.0f / DM);
    const float var  = S2 * (1.0f / DM) - mean * mean;
    const float rstd = rsqrtf(var + 1e-5f);

    float4 gv = *reinterpret_cast<const float4*>(&g[col]);
    float4 bv = *reinterpret_cast<const float4*>(&b[col]);
    float gr[4] = {gv.x, gv.y, gv.z, gv.w};
    float br[4] = {bv.x, bv.y, bv.z, bv.w};
    float4 ov; float* op = &ov.x;
    #pragma unroll
    for (int c = 0; c < 4; c++)
        op[c] = (v[c] - mean) * rstd * gr[c] + br[c];
    *reinterpret_cast<float4*>(&out[(size_t)row * DM + col]) = ov;
}

// ---------------------------------------------------------------------------
extern "C" void kernel_launch(void* const* d_in, const int* in_sizes, int n_in,
                              void* d_out, int out_size)
{
    const float* h    = (const float*)d_in[0];
    const int*   adj  = (const int*)d_in[1];
    const float* Wq   = (const float*)d_in[2];
    const float* bq   = (const float*)d_in[3];
    const float* Wk   = (const float*)d_in[4];
    const float* bk   = (const float*)d_in[5];
    const float* Wv   = (const float*)d_in[6];
    const float* bv   = (const float*)d_in[7];
    const float* Wo   = (const float*)d_in[8];
    const float* bo   = (const float*)d_in[9];
    const float* W1   = (const float*)d_in[10];
    const float* b1   = (const float*)d_in[11];
    const float* W2   = (const float*)d_in[12];
    const float* b2   = (const float*)d_in[13];
    const float* ln1g = (const float*)d_in[14];
    const float* ln1b = (const float*)d_in[15];
    const float* ln2g = (const float*)d_in[16];
    const float* ln2b = (const float*)d_in[17];
    float* out = (float*)d_out;

    float *Qd, *Kd, *Vd, *ctx, *tmp, *h1, *ff;
    cudaGetSymbolAddress((void**)&Qd,  g_Q);
    cudaGetSymbolAddress((void**)&Kd,  g_K);
    cudaGetSymbolAddress((void**)&Vd,  g_V);
    cudaGetSymbolAddress((void**)&ctx, g_ctx);
    cudaGetSymbolAddress((void**)&tmp, g_tmp);
    cudaGetSymbolAddress((void**)&h1,  g_h1);
    cudaGetSymbolAddress((void**)&ff,  g_ff);

    __nv_bfloat16 *hb_hi, *hb_lo, *cx_hi, *cx_lo, *h1_hi, *h1_lo, *ff_hi, *ff_lo, *w_hi, *w_lo;
    cudaGetSymbolAddress((void**)&hb_hi, g_hb_hi);
    cudaGetSymbolAddress((void**)&hb_lo, g_hb_lo);
    cudaGetSymbolAddress((void**)&cx_hi, g_cx_hi);
    cudaGetSymbolAddress((void**)&cx_lo, g_cx_lo);
    cudaGetSymbolAddress((void**)&h1_hi, g_h1_hi);
    cudaGetSymbolAddress((void**)&h1_lo, g_h1_lo);
    cudaGetSymbolAddress((void**)&ff_hi, g_ff_hi);
    cudaGetSymbolAddress((void**)&ff_lo, g_ff_lo);
    cudaGetSymbolAddress((void**)&w_hi,  g_w_hi);
    cudaGetSymbolAddress((void**)&w_lo,  g_w_lo);

    const int ACT = N_TOK * DM;          // 2M elems
    const int WSQ = 512 * 512;           // 256K
    const int WFF = 2048 * 512;          // 1M
    const int FFE = N_TOK * DFF;         // 8M

    // conversions (bandwidth-bound)
    convert_split<<<ACT / 1024, 256>>>(h,  hb_hi, hb_lo, ACT);
    convert_split<<<WSQ / 1024, 256>>>(Wq, w_hi + WOFF_Q, w_lo + WOFF_Q, WSQ);
    convert_split<<<WSQ / 1024, 256>>>(Wk, w_hi + WOFF_K, w_lo + WOFF_K, WSQ);
    convert_split<<<WSQ / 1024, 256>>>(Wv, w_hi + WOFF_V, w_lo + WOFF_V, WSQ);
    convert_split<<<WSQ / 1024, 256>>>(Wo, w_hi + WOFF_O, w_lo + WOFF_O, WSQ);
    convert_split<<<WFF / 1024, 256>>>(W1, w_hi + WOFF_1, w_lo + WOFF_1, WFF);
    convert_split<<<WFF / 1024, 256>>>(W2, w_hi + WOFF_2, w_lo + WOFF_2, WFF);

    const dim3 blk(128);
    const dim3 gQKV(DM / 64, N_TOK / 64, 3);
    const dim3 gP(DM / 64, N_TOK / 64);
    const dim3 gF1(DFF / 64, N_TOK / 64);
    const dim3 gA(N_TOK / 64, NH);

    gemm_mma_qkv<<<gQKV, blk>>>(hb_hi, hb_lo, bq, bk, bv, Qd, Kd, Vd);

    attn_kernel<<<gA, 256>>>(Qd, Kd, Vd, adj, ctx);

    convert_split<<<ACT / 1024, 256>>>(ctx, cx_hi, cx_lo, ACT);
    gemm_mma<false><<<gP, blk>>>(cx_hi, cx_lo, w_hi + WOFF_O, w_lo + WOFF_O, bo, tmp, DM, DM);
    ln_kernel<<<N_TOK, 128>>>(h, tmp, ln1g, ln1b, h1);

    convert_split<<<ACT / 1024, 256>>>(h1, h1_hi, h1_lo, ACT);
    gemm_mma<true ><<<gF1, blk>>>(h1_hi, h1_lo, w_hi + WOFF_1, w_lo + WOFF_1, b1, ff, DFF, DM);

    convert_split<<<FFE / 1024, 256>>>(ff, ff_hi, ff_lo, FFE);
    gemm_mma<false><<<gP, blk>>>(ff_hi, ff_lo, w_hi + WOFF_2, w_lo + WOFF_2, b2, tmp, DM, DFF);
    ln_kernel<<<N_TOK, 128>>>(h1, tmp, ln2g, ln2b, out);
}

// round 7
// speedup vs baseline: 3.2061x; 2.4037x over previous
#include <cuda_runtime.h>
#include <cuda_bf16.h>
#include <cstdint>

#define N_TOK 4096
#define DM    512
#define NH    8
#define DKH   64
#define DFF   2048

// ---------------- scratch (device globals; no runtime allocation) ----------
__device__ float g_Q[N_TOK * DM];
__device__ float g_K[N_TOK * DM];
__device__ float g_V[N_TOK * DM];
__device__ float g_ctx[N_TOK * DM];
__device__ float g_tmp[N_TOK * DM];
__device__ float g_h1[N_TOK * DM];
__device__ float g_ff[(size_t)N_TOK * DFF];

// bf16 hi/lo planes for GEMMs
__device__ __nv_bfloat16 g_hb_hi[N_TOK * DM],  g_hb_lo[N_TOK * DM];
__device__ __nv_bfloat16 g_cx_hi[N_TOK * DM],  g_cx_lo[N_TOK * DM];
__device__ __nv_bfloat16 g_h1_hi[N_TOK * DM],  g_h1_lo[N_TOK * DM];
__device__ __nv_bfloat16 g_ff_hi[(size_t)N_TOK * DFF], g_ff_lo[(size_t)N_TOK * DFF];
#define WOFF_Q  0
#define WOFF_K  (512 * 512)
#define WOFF_V  (2 * 512 * 512)
#define WOFF_O  (3 * 512 * 512)
#define WOFF_1  (4 * 512 * 512)
#define WOFF_2  (4 * 512 * 512 + 2048 * 512)
#define WTOT    (4 * 512 * 512 + 2 * 2048 * 512)
__device__ __nv_bfloat16 g_w_hi[WTOT], g_w_lo[WTOT];

// attention: per-head bf16 planes [h][tok][64], V transposed [h][d][tok]
__device__ __nv_bfloat16 g_qs_hi[NH * N_TOK * DKH], g_qs_lo[NH * N_TOK * DKH];
__device__ __nv_bfloat16 g_ks_hi[NH * N_TOK * DKH], g_ks_lo[NH * N_TOK * DKH];
__device__ __nv_bfloat16 g_vt[NH * DKH * N_TOK];
// adjacency bitmask (diag folded in): [tok][64] uint64
__device__ unsigned long long g_adjb[N_TOK * (N_TOK / 64)];

// ===================== low-level helpers ==================================
__device__ __forceinline__ uint32_t smem_u32(const void* p) {
    uint32_t a;
    asm("{ .reg .u64 t; cvta.to.shared.u64 t, %1; cvt.u32.u64 %0, t; }"
        : "=r"(a) : "l"(p));
    return a;
}
__device__ __forceinline__ void cp16(uint32_t dst, const void* src) {
    asm volatile("cp.async.cg.shared.global [%0], [%1], 16;" :: "r"(dst), "l"(src));
}
__device__ __forceinline__ void cp_commit_wait() {
    asm volatile("cp.async.commit_group;");
    asm volatile("cp.async.wait_group 0;" ::: "memory");
}
__device__ __forceinline__ void ldm_x4(uint32_t* r, uint32_t addr) {
    asm volatile("ldmatrix.sync.aligned.m8n8.x4.shared.b16 {%0,%1,%2,%3}, [%4];"
                 : "=r"(r[0]), "=r"(r[1]), "=r"(r[2]), "=r"(r[3]) : "r"(addr));
}
__device__ __forceinline__ void mma_bf16(float* d, const uint32_t* a, const uint32_t* b) {
    asm volatile("mma.sync.aligned.m16n8k16.row.col.f32.bf16.bf16.f32 "
                 "{%0,%1,%2,%3},{%4,%5,%6,%7},{%8,%9},{%0,%1,%2,%3};"
                 : "+f"(d[0]), "+f"(d[1]), "+f"(d[2]), "+f"(d[3])
                 : "r"(a[0]), "r"(a[1]), "r"(a[2]), "r"(a[3]),
                   "r"(b[0]), "r"(b[1]));
}
// 2^(s-8) without MUFU; valid for s in [-110, 100]
__device__ __forceinline__ float fexp2b(float s) {
    const float C1 = 12582904.0f;                 // 1.5*2^23 - 8
    float t  = s + C1;
    float v  = t - C1;                            // round(s-8) + 8
    float zf = s - v;                             // [-0.5, 0.5]
    int   zi = __float_as_int(t) - 0x4B400000;    // round(s-8)
    float p = fmaf(zf, 0.00961813f, 0.05550411f);
    p = fmaf(zf, p, 0.24022651f);
    p = fmaf(zf, p, 0.69314718f);
    p = fmaf(zf, p, 1.0f);
    return __int_as_float(__float_as_int(p) + (zi << 23));
}

// ===================== fp32 -> bf16 hi/lo conversion (flat) ================
__global__ __launch_bounds__(256) void convert_split(const float* __restrict__ in,
                                                     __nv_bfloat16* __restrict__ hi,
                                                     __nv_bfloat16* __restrict__ lo,
                                                     int n)
{
    int i = (blockIdx.x * 256 + threadIdx.x) * 4;
    if (i >= n) return;
    float4 v = *reinterpret_cast<const float4*>(in + i);
    __nv_bfloat16 hx = __float2bfloat16(v.x), hy = __float2bfloat16(v.y);
    __nv_bfloat16 hz = __float2bfloat16(v.z), hw = __float2bfloat16(v.w);
    __nv_bfloat162 h0; h0.x = hx; h0.y = hy;
    __nv_bfloat162 h1; h1.x = hz; h1.y = hw;
    __nv_bfloat162 l0, l1;
    l0.x = __float2bfloat16(v.x - __bfloat162float(hx));
    l0.y = __float2bfloat16(v.y - __bfloat162float(hy));
    l1.x = __float2bfloat16(v.z - __bfloat162float(hz));
    l1.y = __float2bfloat16(v.w - __bfloat162float(hw));
    *reinterpret_cast<__nv_bfloat162*>(hi + i)     = h0;
    *reinterpret_cast<__nv_bfloat162*>(hi + i + 2) = h1;
    *reinterpret_cast<__nv_bfloat162*>(lo + i)     = l0;
    *reinterpret_cast<__nv_bfloat162*>(lo + i + 2) = l1;
}

// fp32 [tok][512] -> per-head split planes [h][tok][64], optional scale
__global__ __launch_bounds__(256) void convert_split_heads(const float* __restrict__ in,
                                                           __nv_bfloat16* __restrict__ hi,
                                                           __nv_bfloat16* __restrict__ lo,
                                                           float scale)
{
    int i = (blockIdx.x * 256 + threadIdx.x) * 4;   // over N_TOK*DM
    int tok = i >> 9, col = i & 511;
    int h = col >> 6, d = col & 63;
    size_t dst = (size_t)h * (N_TOK * DKH) + (size_t)tok * DKH + d;
    float4 v = *reinterpret_cast<const float4*>(in + i);
    v.x *= scale; v.y *= scale; v.z *= scale; v.w *= scale;
    __nv_bfloat16 hx = __float2bfloat16(v.x), hy = __float2bfloat16(v.y);
    __nv_bfloat16 hz = __float2bfloat16(v.z), hw = __float2bfloat16(v.w);
    __nv_bfloat162 h0; h0.x = hx; h0.y = hy;
    __nv_bfloat162 h1; h1.x = hz; h1.y = hw;
    __nv_bfloat162 l0, l1;
    l0.x = __float2bfloat16(v.x - __bfloat162float(hx));
    l0.y = __float2bfloat16(v.y - __bfloat162float(hy));
    l1.x = __float2bfloat16(v.z - __bfloat162float(hz));
    l1.y = __float2bfloat16(v.w - __bfloat162float(hw));
    *reinterpret_cast<__nv_bfloat162*>(hi + dst)     = h0;
    *reinterpret_cast<__nv_bfloat162*>(hi + dst + 2) = h1;
    *reinterpret_cast<__nv_bfloat162*>(lo + dst)     = l0;
    *reinterpret_cast<__nv_bfloat162*>(lo + dst + 2) = l1;
}

// V fp32 [tok][512] -> bf16 transposed [h][d][tok]
__global__ __launch_bounds__(256) void convert_v_t(const float* __restrict__ V,
                                                   __nv_bfloat16* __restrict__ vt)
{
    __shared__ float sm[64][65];
    const int h = blockIdx.y, t0 = blockIdx.x * 64;
    const int tid = threadIdx.x;
    for (int i = tid; i < 1024; i += 256) {
        int r = i >> 4, c4 = (i & 15) * 4;
        float4 v = *reinterpret_cast<const float4*>(&V[(size_t)(t0 + r) * DM + h * DKH + c4]);
        sm[c4][r] = v.x; sm[c4 + 1][r] = v.y; sm[c4 + 2][r] = v.z; sm[c4 + 3][r] = v.w;
    }
    __syncthreads();
    for (int i = tid; i < 2048; i += 256) {
        int d = i >> 5, pr = i & 31;
        __nv_bfloat162 b = __floats2bfloat162_rn(sm[d][2 * pr], sm[d][2 * pr + 1]);
        *reinterpret_cast<__nv_bfloat162*>(
            vt + (size_t)h * (DKH * N_TOK) + (size_t)d * N_TOK + t0 + 2 * pr) = b;
    }
}

// adj int32 -> bitmask, diag folded in
__global__ __launch_bounds__(256) void pack_adj(const int* __restrict__ adj,
                                                unsigned long long* __restrict__ bits)
{
    int gid = blockIdx.x * 256 + threadIdx.x;   // N_TOK * 64 words
    int r = gid >> 6, w = gid & 63;
    const int4* p = reinterpret_cast<const int4*>(adj + (size_t)r * N_TOK + w * 64);
    unsigned long long b = 0;
    #pragma unroll
    for (int i = 0; i < 16; i++) {
        int4 a = p[i];
        if (a.x) b |= 1ull << (i * 4 + 0);
        if (a.y) b |= 1ull << (i * 4 + 1);
        if (a.z) b |= 1ull << (i * 4 + 2);
        if (a.w) b |= 1ull << (i * 4 + 3);
    }
    if ((r >> 6) == w) b |= 1ull << (r & 63);
    bits[gid] = b;
}

// ===================== tensor-core split-bf16 GEMM (unchanged, R6) ========
#define SROW 80

template <bool RELU>
__device__ __forceinline__ void gemm_mma_body(const __nv_bfloat16* __restrict__ Ahi,
                                              const __nv_bfloat16* __restrict__ Alo,
                                              const __nv_bfloat16* __restrict__ Bhi,
                                              const __nv_bfloat16* __restrict__ Blo,
                                              const float* __restrict__ bias,
                                              float* __restrict__ C,
                                              int Nn, int K)
{
    __shared__ __align__(128) uint8_t s_ahi[64 * SROW];
    __shared__ __align__(128) uint8_t s_alo[64 * SROW];
    __shared__ __align__(128) uint8_t s_bhi[64 * SROW];
    __shared__ __align__(128) uint8_t s_blo[64 * SROW];

    const int tid = threadIdx.x;
    const int lid = tid & 31;
    const int wid = tid >> 5;
    const int wm  = (wid >> 1) * 32;
    const int wn  = (wid & 1) * 32;
    const int m0  = blockIdx.y * 64;
    const int n0  = blockIdx.x * 64;

    const uint32_t sa_hi = smem_u32(s_ahi), sa_lo = smem_u32(s_alo);
    const uint32_t sb_hi = smem_u32(s_bhi), sb_lo = smem_u32(s_blo);

    const int r0 = tid >> 2, u0 = tid & 3;
    const int r1 = (tid + 128) >> 2;
    const int dst_off0 = r0 * SROW + u0 * 16;
    const int dst_off1 = r1 * SROW + u0 * 16;

    const __nv_bfloat16* gA_hi = Ahi + (size_t)m0 * K;
    const __nv_bfloat16* gA_lo = Alo + (size_t)m0 * K;
    const __nv_bfloat16* gB_hi = Bhi + (size_t)n0 * K;
    const __nv_bfloat16* gB_lo = Blo + (size_t)n0 * K;

    float acc[2][4][4] = {};

    const int a_row = (lid & 15);
    const int a_sel = (lid >> 4);
    const int b_row = ((lid >> 4) & 1) * 8 + (lid & 7);
    const int b_sel = ((lid >> 3) & 1);

    const int nch = K >> 5;
    for (int c = 0; c < nch; c++) {
        const int k0 = c * 32;
        const int go0 = r0 * K + k0 + u0 * 8;
        const int go1 = r1 * K + k0 + u0 * 8;
        cp16(sa_hi + dst_off0, gA_hi + go0); cp16(sa_hi + dst_off1, gA_hi + go1);
        cp16(sa_lo + dst_off0, gA_lo + go0); cp16(sa_lo + dst_off1, gA_lo + go1);
        cp16(sb_hi + dst_off0, gB_hi + go0); cp16(sb_hi + dst_off1, gB_hi + go1);
        cp16(sb_lo + dst_off0, gB_lo + go0); cp16(sb_lo + dst_off1, gB_lo + go1);
        cp_commit_wait();
        __syncthreads();

        #pragma unroll
        for (int s = 0; s < 2; s++) {
            uint32_t afh[2][4], afl[2][4], bfh[2][4], bfl[2][4];
            #pragma unroll
            for (int mt = 0; mt < 2; mt++) {
                const uint32_t aoff = (uint32_t)((wm + mt * 16 + a_row) * SROW
                                                 + (s * 2 + a_sel) * 16);
                ldm_x4(afh[mt], sa_hi + aoff);
                ldm_x4(afl[mt], sa_lo + aoff);
            }
            #pragma unroll
            for (int q = 0; q < 2; q++) {
                const uint32_t boff = (uint32_t)((wn + q * 16 + b_row) * SROW
                                                 + (s * 2 + b_sel) * 16);
                ldm_x4(bfh[q], sb_hi + boff);
                ldm_x4(bfl[q], sb_lo + boff);
            }
            #pragma unroll
            for (int mt = 0; mt < 2; mt++)
                #pragma unroll
                for (int q = 0; q < 2; q++)
                    #pragma unroll
                    for (int t2 = 0; t2 < 2; t2++) {
                        float* d = acc[mt][q * 2 + t2];
                        mma_bf16(d, afh[mt], &bfh[q][t2 * 2]);
                        mma_bf16(d, afh[mt], &bfl[q][t2 * 2]);
                        mma_bf16(d, afl[mt], &bfh[q][t2 * 2]);
                    }
        }
        __syncthreads();
    }

    #pragma unroll
    for (int mt = 0; mt < 2; mt++) {
        const int row = m0 + wm + mt * 16 + (lid >> 2);
        #pragma unroll
        for (int nt = 0; nt < 4; nt++) {
            const int col = n0 + wn + nt * 8 + (lid & 3) * 2;
            const float bx = bias[col], by = bias[col + 1];
            float2 v0, v1;
            v0.x = acc[mt][nt][0] + bx; v0.y = acc[mt][nt][1] + by;
            v1.x = acc[mt][nt][2] + bx; v1.y = acc[mt][nt][3] + by;
            if (RELU) {
                v0.x = fmaxf(v0.x, 0.0f); v0.y = fmaxf(v0.y, 0.0f);
                v1.x = fmaxf(v1.x, 0.0f); v1.y = fmaxf(v1.y, 0.0f);
            }
            *reinterpret_cast<float2*>(C + (size_t)row * Nn + col)       = v0;
            *reinterpret_cast<float2*>(C + (size_t)(row + 8) * Nn + col) = v1;
        }
    }
}

template <bool RELU>
__global__ __launch_bounds__(128) void gemm_mma(const __nv_bfloat16* __restrict__ Ahi,
                                                const __nv_bfloat16* __restrict__ Alo,
                                                const __nv_bfloat16* __restrict__ Bhi,
                                                const __nv_bfloat16* __restrict__ Blo,
                                                const float* __restrict__ bias,
                                                float* __restrict__ C,
                                                int Nn, int K)
{
    gemm_mma_body<RELU>(Ahi, Alo, Bhi, Blo, bias, C, Nn, K);
}

__global__ __launch_bounds__(128) void gemm_mma_qkv(const __nv_bfloat16* __restrict__ Ahi,
                                                    const __nv_bfloat16* __restrict__ Alo,
                                                    const float* __restrict__ bq,
                                                    const float* __restrict__ bk,
                                                    const float* __restrict__ bv,
                                                    float* __restrict__ Qo,
                                                    float* __restrict__ Ko,
                                                    float* __restrict__ Vo)
{
    const __nv_bfloat16* whi; const __nv_bfloat16* wlo;
    const float* bias; float* C;
    if (blockIdx.z == 0)      { whi = g_w_hi + WOFF_Q; wlo = g_w_lo + WOFF_Q; bias = bq; C = Qo; }
    else if (blockIdx.z == 1) { whi = g_w_hi + WOFF_K; wlo = g_w_lo + WOFF_K; bias = bk; C = Ko; }
    else                      { whi = g_w_hi + WOFF_V; wlo = g_w_lo + WOFF_V; bias = bv; C = Vo; }
    gemm_mma_body<false>(Ahi, Alo, whi, wlo, bias, C, DM, DM);
}

// ===================== tensor-core flash attention ========================
// block: (head, 64-q-tile), 4 warps x m16. Fixed-shift softmax (no max pass).
__global__ __launch_bounds__(128) void attn_mma(
    const __nv_bfloat16* __restrict__ qhi, const __nv_bfloat16* __restrict__ qlo,
    const __nv_bfloat16* __restrict__ khi, const __nv_bfloat16* __restrict__ klo,
    const __nv_bfloat16* __restrict__ vt,
    const unsigned long long* __restrict__ adjb,
    float* __restrict__ ctx)
{
    __shared__ __align__(128) uint8_t s_khi[2 * 64 * SROW];
    __shared__ __align__(128) uint8_t s_klo[2 * 64 * SROW];
    __shared__ __align__(128) uint8_t s_vt [2 * 64 * SROW];

    const int tid = threadIdx.x, lid = tid & 31, wid = tid >> 5;
    const int h = blockIdx.y, q0 = blockIdx.x * 64;
    const int wm = wid * 16;
    const size_t hoff = (size_t)h * (N_TOK * DKH);

    const uint32_t skhi = smem_u32(s_khi), sklo = smem_u32(s_klo), svt = smem_u32(s_vt);

    // Q a-fragments straight from global (loaded once)
    uint32_t qa_h[4][4], qa_l[4][4];
    const int rr0 = q0 + wm + (lid >> 2);
    {
        const int cc = (lid & 3) * 2;
        #pragma unroll
        for (int ks = 0; ks < 4; ks++) {
            const size_t o0 = hoff + (size_t)rr0 * 64 + ks * 16 + cc;
            const size_t o1 = hoff + (size_t)(rr0 + 8) * 64 + ks * 16 + cc;
            qa_h[ks][0] = *reinterpret_cast<const uint32_t*>(qhi + o0);
            qa_h[ks][1] = *reinterpret_cast<const uint32_t*>(qhi + o1);
            qa_h[ks][2] = *reinterpret_cast<const uint32_t*>(qhi + o0 + 8);
            qa_h[ks][3] = *reinterpret_cast<const uint32_t*>(qhi + o1 + 8);
            qa_l[ks][0] = *reinterpret_cast<const uint32_t*>(qlo + o0);
            qa_l[ks][1] = *reinterpret_cast<const uint32_t*>(qlo + o1);
            qa_l[ks][2] = *reinterpret_cast<const uint32_t*>(qlo + o0 + 8);
            qa_l[ks][3] = *reinterpret_cast<const uint32_t*>(qlo + o1 + 8);
        }
    }

    const int b_row = ((lid >> 4) & 1) * 8 + (lid & 7);
    const int b_sel = (lid >> 3) & 1;

    float o_acc[8][4] = {};
    float lsum0 = 0.0f, lsum1 = 0.0f;

    // prologue load of kv block 0
    {
        #pragma unroll
        for (int i = 0; i < 4; i++) {
            const int idx = tid + i * 128;
            const int row = idx >> 3, ch = (idx >> 2) & 1, u = idx & 3;
            const uint32_t doff = (uint32_t)((ch * 64 + row) * SROW + u * 16);
            cp16(skhi + doff, khi + hoff + (size_t)row * 64 + ch * 32 + u * 8);
            cp16(sklo + doff, klo + hoff + (size_t)row * 64 + ch * 32 + u * 8);
            cp16(svt  + doff, vt  + hoff + (size_t)row * N_TOK + ch * 32 + u * 8);
        }
        asm volatile("cp.async.commit_group;");
    }

    for (int kb = 0; kb < N_TOK / 64; kb++) {
        asm volatile("cp.async.wait_group 0;" ::: "memory");
        __syncthreads();

        // S = Qhi*Khi + Qhi*Klo + Qlo*Khi
        float sc[8][4] = {};
        #pragma unroll
        for (int ks = 0; ks < 4; ks++) {
            const uint32_t base = (uint32_t)(((ks >> 1) * 64 + b_row) * SROW
                                             + ((ks & 1) * 2 + b_sel) * 16);
            #pragma unroll
            for (int t = 0; t < 4; t++) {
                uint32_t bh[4], bl[4];
                ldm_x4(bh, skhi + base + t * 16 * SROW);
                ldm_x4(bl, sklo + base + t * 16 * SROW);
                #pragma unroll
                for (int t2 = 0; t2 < 2; t2++) {
                    float* d = sc[t * 2 + t2];
                    mma_bf16(d, qa_h[ks], &bh[t2 * 2]);
                    mma_bf16(d, qa_h[ks], &bl[t2 * 2]);
                    mma_bf16(d, qa_l[ks], &bh[t2 * 2]);
                }
            }
        }

        // mask + exp2(s-8); pack P fragments for PV
        const unsigned long long w0 = adjb[(size_t)rr0 * 64 + kb];
        const unsigned long long w1 = adjb[(size_t)(rr0 + 8) * 64 + kb];
        uint32_t pa[4][4];
        #pragma unroll
        for (int f = 0; f < 8; f++) {
            const int cb = f * 8 + (lid & 3) * 2;
            const float s0 = ((w0 >> cb) & 1)       ? sc[f][0] : -102.0f;
            const float s1 = ((w0 >> (cb + 1)) & 1) ? sc[f][1] : -102.0f;
            const float s2 = ((w1 >> cb) & 1)       ? sc[f][2] : -102.0f;
            const float s3 = ((w1 >> (cb + 1)) & 1) ? sc[f][3] : -102.0f;
            const float p0 = fexp2b(s0), p1 = fexp2b(s1);
            const float p2 = fexp2b(s2), p3 = fexp2b(s3);
            lsum0 += p0 + p1; lsum1 += p2 + p3;
            __nv_bfloat162 x01 = __floats2bfloat162_rn(p0, p1);
            __nv_bfloat162 x23 = __floats2bfloat162_rn(p2, p3);
            const int j = f >> 1, oo = (f & 1) * 2;
            pa[j][oo]     = *reinterpret_cast<uint32_t*>(&x01);
            pa[j][oo + 1] = *reinterpret_cast<uint32_t*>(&x23);
        }

        // O += P * V^T   (Vt rows = d, k = kv)
        #pragma unroll
        for (int ks = 0; ks < 4; ks++) {
            const uint32_t base = (uint32_t)(((ks >> 1) * 64 + b_row) * SROW
                                             + ((ks & 1) * 2 + b_sel) * 16);
            #pragma unroll
            for (int t = 0; t < 4; t++) {
                uint32_t bv[4];
                ldm_x4(bv, svt + base + t * 16 * SROW);
                mma_bf16(o_acc[t * 2],     pa[ks], &bv[0]);
                mma_bf16(o_acc[t * 2 + 1], pa[ks], &bv[2]);
            }
        }

        __syncthreads();
        if (kb < N_TOK / 64 - 1) {
            const int k0 = (kb + 1) * 64;
            #pragma unroll
            for (int i = 0; i < 4; i++) {
                const int idx = tid + i * 128;
                const int row = idx >> 3, ch = (idx >> 2) & 1, u = idx & 3;
                const uint32_t doff = (uint32_t)((ch * 64 + row) * SROW + u * 16);
                cp16(skhi + doff, khi + hoff + (size_t)(k0 + row) * 64 + ch * 32 + u * 8);
                cp16(sklo + doff, klo + hoff + (size_t)(k0 + row) * 64 + ch * 32 + u * 8);
                cp16(svt  + doff, vt  + hoff + (size_t)row * N_TOK + k0 + ch * 32 + u * 8);
            }
            asm volatile("cp.async.commit_group;");
        }
    }

    // reduce l across the 4 lanes sharing each row, normalize, store
    lsum0 += __shfl_xor_sync(0xffffffffu, lsum0, 1);
    lsum0 += __shfl_xor_sync(0xffffffffu, lsum0, 2);
    lsum1 += __shfl_xor_sync(0xffffffffu, lsum1, 1);
    lsum1 += __shfl_xor_sync(0xffffffffu, lsum1, 2);
    const float inv0 = 1.0f / lsum0, inv1 = 1.0f / lsum1;
    const int col0 = h * DKH + (lid & 3) * 2;
    #pragma unroll
    for (int f = 0; f < 8; f++) {
        float2 v0 = make_float2(o_acc[f][0] * inv0, o_acc[f][1] * inv0);
        float2 v1 = make_float2(o_acc[f][2] * inv1, o_acc[f][3] * inv1);
        *reinterpret_cast<float2*>(ctx + (size_t)rr0 * DM + col0 + f * 8)       = v0;
        *reinterpret_cast<float2*>(ctx + (size_t)(rr0 + 8) * DM + col0 + f * 8) = v1;
    }
}

// ---------------------------------------------------------------------------
// out = LayerNorm(x + r) * g + b
// ---------------------------------------------------------------------------
__global__ __launch_bounds__(128) void ln_kernel(const float* __restrict__ x,
                                                 const float* __restrict__ r,
                                                 const float* __restrict__ g,
                                                 const float* __restrict__ b,
                                                 float* __restrict__ out)
{
    __shared__ float ws[4], ws2[4];
    const int row = blockIdx.x;
    const int tid = threadIdx.x;
    const int col = tid * 4;

    float4 xv = *reinterpret_cast<const float4*>(&x[(size_t)row * DM + col]);
    float4 rv = *reinterpret_cast<const float4*>(&r[(size_t)row * DM + col]);
    float v[4] = {xv.x + rv.x, xv.y + rv.y, xv.z + rv.z, xv.w + rv.w};

    float s = 0.0f, s2 = 0.0f;
    #pragma unroll
    for (int c = 0; c < 4; c++) { s += v[c]; s2 = fmaf(v[c], v[c], s2); }
    #pragma unroll
    for (int off = 16; off >= 1; off >>= 1) {
        s  += __shfl_xor_sync(0xffffffffu, s,  off);
        s2 += __shfl_xor_sync(0xffffffffu, s2, off);
    }
    const int wid = tid >> 5;
    if ((tid & 31) == 0) { ws[wid] = s; ws2[wid] = s2; }
    __syncthreads();
    const float S  = ws[0] + ws[1] + ws[2] + ws[3];
    const float S2 = ws2[0] + ws2[1] + ws2[2] + ws2[3];
    const float mean = S * (1.0f / DM);
    const float var  = S2 * (1.0f / DM) - mean * mean;
    const float rstd = rsqrtf(var + 1e-5f);

    float4 gv = *reinterpret_cast<const float4*>(&g[col]);
    float4 bv = *reinterpret_cast<const float4*>(&b[col]);
    float gr[4] = {gv.x, gv.y, gv.z, gv.w};
    float br[4] = {bv.x, bv.y, bv.z, bv.w};
    float4 ov; float* op = &ov.x;
    #pragma unroll
    for (int c = 0; c < 4; c++)
        op[c] = (v[c] - mean) * rstd * gr[c] + br[c];
    *reinterpret_cast<float4*>(&out[(size_t)row * DM + col]) = ov;
}

// ---------------------------------------------------------------------------
extern "C" void kernel_launch(void* const* d_in, const int* in_sizes, int n_in,
                              void* d_out, int out_size)
{
    const float* h    = (const float*)d_in[0];
    const int*   adj  = (const int*)d_in[1];
    const float* Wq   = (const float*)d_in[2];
    const float* bq   = (const float*)d_in[3];
    const float* Wk   = (const float*)d_in[4];
    const float* bk   = (const float*)d_in[5];
    const float* Wv   = (const float*)d_in[6];
    const float* bv   = (const float*)d_in[7];
    const float* Wo   = (const float*)d_in[8];
    const float* bo   = (const float*)d_in[9];
    const float* W1   = (const float*)d_in[10];
    const float* b1   = (const float*)d_in[11];
    const float* W2   = (const float*)d_in[12];
    const float* b2   = (const float*)d_in[13];
    const float* ln1g = (const float*)d_in[14];
    const float* ln1b = (const float*)d_in[15];
    const float* ln2g = (const float*)d_in[16];
    const float* ln2b = (const float*)d_in[17];
    float* out = (float*)d_out;

    float *Qd, *Kd, *Vd, *ctx, *tmp, *h1, *ff;
    cudaGetSymbolAddress((void**)&Qd,  g_Q);
    cudaGetSymbolAddress((void**)&Kd,  g_K);
    cudaGetSymbolAddress((void**)&Vd,  g_V);
    cudaGetSymbolAddress((void**)&ctx, g_ctx);
    cudaGetSymbolAddress((void**)&tmp, g_tmp);
    cudaGetSymbolAddress((void**)&h1,  g_h1);
    cudaGetSymbolAddress((void**)&ff,  g_ff);

    __nv_bfloat16 *hb_hi, *hb_lo, *cx_hi, *cx_lo, *h1_hi, *h1_lo, *ff_hi, *ff_lo, *w_hi, *w_lo;
    __nv_bfloat16 *qs_hi, *qs_lo, *ks_hi, *ks_lo, *vtp;
    unsigned long long* adjb;
    cudaGetSymbolAddress((void**)&hb_hi, g_hb_hi);
    cudaGetSymbolAddress((void**)&hb_lo, g_hb_lo);
    cudaGetSymbolAddress((void**)&cx_hi, g_cx_hi);
    cudaGetSymbolAddress((void**)&cx_lo, g_cx_lo);
    cudaGetSymbolAddress((void**)&h1_hi, g_h1_hi);
    cudaGetSymbolAddress((void**)&h1_lo, g_h1_lo);
    cudaGetSymbolAddress((void**)&ff_hi, g_ff_hi);
    cudaGetSymbolAddress((void**)&ff_lo, g_ff_lo);
    cudaGetSymbolAddress((void**)&w_hi,  g_w_hi);
    cudaGetSymbolAddress((void**)&w_lo,  g_w_lo);
    cudaGetSymbolAddress((void**)&qs_hi, g_qs_hi);
    cudaGetSymbolAddress((void**)&qs_lo, g_qs_lo);
    cudaGetSymbolAddress((void**)&ks_hi, g_ks_hi);
    cudaGetSymbolAddress((void**)&ks_lo, g_ks_lo);
    cudaGetSymbolAddress((void**)&vtp,   g_vt);
    cudaGetSymbolAddress((void**)&adjb,  g_adjb);

    const int ACT = N_TOK * DM;
    const int WSQ = 512 * 512;
    const int WFF = 2048 * 512;
    const int FFE = N_TOK * DFF;
    const float QSCALE = 1.4426950408889634f / 8.0f;   // log2(e)/sqrt(d_k)

    // prep (independent of QKV)
    pack_adj<<<(N_TOK * 64) / 256, 256>>>(adj, adjb);
    convert_split<<<ACT / 1024, 256>>>(h,  hb_hi, hb_lo, ACT);
    convert_split<<<WSQ / 1024, 256>>>(Wq, w_hi + WOFF_Q, w_lo + WOFF_Q, WSQ);
    convert_split<<<WSQ / 1024, 256>>>(Wk, w_hi + WOFF_K, w_lo + WOFF_K, WSQ);
    convert_split<<<WSQ / 1024, 256>>>(Wv, w_hi + WOFF_V, w_lo + WOFF_V, WSQ);
    convert_split<<<WSQ / 1024, 256>>>(Wo, w_hi + WOFF_O, w_lo + WOFF_O, WSQ);
    convert_split<<<WFF / 1024, 256>>>(W1, w_hi + WOFF_1, w_lo + WOFF_1, WFF);
    convert_split<<<WFF / 1024, 256>>>(W2, w_hi + WOFF_2, w_lo + WOFF_2, WFF);

    const dim3 blk(128);
    const dim3 gQKV(DM / 64, N_TOK / 64, 3);
    const dim3 gP(DM / 64, N_TOK / 64);
    const dim3 gF1(DFF / 64, N_TOK / 64);

    gemm_mma_qkv<<<gQKV, blk>>>(hb_hi, hb_lo, bq, bk, bv, Qd, Kd, Vd);

    // attention-prep conversions
    convert_split_heads<<<ACT / 1024, 256>>>(Qd, qs_hi, qs_lo, QSCALE);
    convert_split_heads<<<ACT / 1024, 256>>>(Kd, ks_hi, ks_lo, 1.0f);
    convert_v_t<<<dim3(N_TOK / 64, NH), 256>>>(Vd, vtp);

    attn_mma<<<dim3(N_TOK / 64, NH), blk>>>(qs_hi, qs_lo, ks_hi, ks_lo, vtp, adjb, ctx);

    convert_split<<<ACT / 1024, 256>>>(ctx, cx_hi, cx_lo, ACT);
    gemm_mma<false><<<gP, blk>>>(cx_hi, cx_lo, w_hi + WOFF_O, w_lo + WOFF_O, bo, tmp, DM, DM);
    ln_kernel<<<N_TOK, 128>>>(h, tmp, ln1g, ln1b, h1);

    convert_split<<<ACT / 1024, 256>>>(h1, h1_hi, h1_lo, ACT);
    gemm_mma<true ><<<gF1, blk>>>(h1_hi, h1_lo, w_hi + WOFF_1, w_lo + WOFF_1, b1, ff, DFF, DM);

    convert_split<<<FFE / 1024, 256>>>(ff, ff_hi, ff_lo, FFE);
    gemm_mma<false><<<gP, blk>>>(ff_hi, ff_lo, w_hi + WOFF_2, w_lo + WOFF_2, b2, tmp, DM, DFF);
    ln_kernel<<<N_TOK, 128>>>(h1, tmp, ln2g, ln2b, out);
}